// round 1
// baseline (speedup 1.0000x reference)
#include <cuda_runtime.h>
#include <cstddef>

// Problem constants
#define Bn   64
#define Dd   1024        // D_IN = D_OUT = 1024
#define MAT  (Dd*Dd)     // 1048576

// Scratch: tmp[n] = W @ a_cov[n]   (64 * 1M floats = 256 MB)
__device__ float g_tmp[(size_t)Bn * MAT];
__device__ float g_part[Bn * 8];
__device__ float g_st[Bn];

// ---------------------------------------------------------------------------
// Kernel 1: h_mean[n,k] = sum_i a_mean[n,i] * W[k,i] + bias[k]
// grid (4, 64), block 256
// ---------------------------------------------------------------------------
__global__ void hmean_kernel(const float* __restrict__ a_mean,
                             const float* __restrict__ W,
                             const float* __restrict__ bias,
                             float* __restrict__ out)
{
    int n = blockIdx.y;
    int k = blockIdx.x * 256 + threadIdx.x;
    __shared__ float sh_a[Dd];
    for (int i = threadIdx.x; i < Dd; i += 256) sh_a[i] = a_mean[n * Dd + i];
    __syncthreads();

    const float4* w4 = reinterpret_cast<const float4*>(W + (size_t)k * Dd);
    float acc = bias[k];
#pragma unroll 8
    for (int i = 0; i < Dd / 4; i++) {
        float4 w = w4[i];
        acc += w.x * sh_a[4*i] + w.y * sh_a[4*i+1] + w.z * sh_a[4*i+2] + w.w * sh_a[4*i+3];
    }
    out[(size_t)n * Dd + k] = acc;
}

// ---------------------------------------------------------------------------
// Kernel 2: partial[n,slice] = sum over rows i in slice of
//           sum_j A[i,j] * (a_cov[n,i,j] + a[i]*a[j])
// grid (8, 64), block 256. Deterministic two-stage reduction (no atomics).
// ---------------------------------------------------------------------------
__global__ void st_kernel(const float* __restrict__ a_mean,
                          const float* __restrict__ a_cov,
                          const float* __restrict__ kfA)
{
    int n = blockIdx.y;
    int slice = blockIdx.x;      // 0..7 (rows slice*128 .. +127)
    int tid = threadIdx.x;

    __shared__ float sh_a[Dd];
    for (int i = tid; i < Dd; i += 256) sh_a[i] = a_mean[n * Dd + i];
    __syncthreads();

    const float4* cov4 = reinterpret_cast<const float4*>(a_cov + (size_t)n * MAT);
    const float4* A4   = reinterpret_cast<const float4*>(kfA);

    float local = 0.f;
    int base = slice * (128 * 256);          // float4 index base (256 f4 per row)
    for (int idx = base + tid; idx < base + 128 * 256; idx += 256) {
        int i  = idx >> 8;                   // row index
        int j4 = (idx & 255) * 4;            // col base
        float ai = sh_a[i];
        float4 a = A4[idx];
        float4 c = cov4[idx];
        local += a.x * (c.x + ai * sh_a[j4 + 0])
               + a.y * (c.y + ai * sh_a[j4 + 1])
               + a.z * (c.z + ai * sh_a[j4 + 2])
               + a.w * (c.w + ai * sh_a[j4 + 3]);
    }

    __shared__ float red[256];
    red[tid] = local;
    __syncthreads();
    for (int s = 128; s > 0; s >>= 1) {
        if (tid < s) red[tid] += red[tid + s];
        __syncthreads();
    }
    if (tid == 0) g_part[n * 8 + slice] = red[0];
}

__global__ void st_reduce_kernel()
{
    int n = threadIdx.x;   // 64 threads
    float s = 0.f;
#pragma unroll
    for (int i = 0; i < 8; i++) s += g_part[n * 8 + i];
    g_st[n] = s;
}

// ---------------------------------------------------------------------------
// Tiled SGEMM: C[n] = A[n] * B[n] (+ epilogue), M=N=K=1024.
// BM=BN=128, BK=8, 256 threads, 8x8 microtile per thread (split 64+64).
// TRANSB=false : C[m,q] = sum_k A[m,k] * B[k,q]
// TRANSB=true  : C[m,q] = sum_k A[m,k] * B[q,k]
// EPI=true     : C += st[n]*kfB + bcov
// ---------------------------------------------------------------------------
template<bool TRANSB, bool EPI>
__global__ __launch_bounds__(256, 2)
void gemm128(const float* __restrict__ A, const float* __restrict__ B,
             float* __restrict__ C,
             const float* __restrict__ kfB, const float* __restrict__ bcov,
             size_t strideA, size_t strideB, size_t strideC)
{
    const int n = blockIdx.z;
    A += (size_t)n * strideA;
    B += (size_t)n * strideB;
    C += (size_t)n * strideC;

    __shared__ __align__(16) float As[8][128];
    __shared__ __align__(16) float Bs[8][128];

    const int tid = threadIdx.x;
    const int tx = tid & 15;          // 0..15 (column group)
    const int ty = tid >> 4;          // 0..15 (row group)

    // loader indices (shared by A and transposed-B)
    const int lrow = tid >> 1;        // 0..127
    const int lcol = (tid & 1) * 4;   // 0 or 4

    const float* Ap = A + ((size_t)(blockIdx.y * 128 + lrow)) * Dd + lcol;
    const float* Bp;
    const int brow = tid >> 5;            // 0..7 (NN loader)
    const int bcol = (tid & 31) * 4;
    if (TRANSB) {
        Bp = B + ((size_t)(blockIdx.x * 128 + lrow)) * Dd + lcol;
    } else {
        Bp = B + (size_t)brow * Dd + blockIdx.x * 128 + bcol;
    }

    float acc[8][8];
#pragma unroll
    for (int i = 0; i < 8; i++)
#pragma unroll
        for (int j = 0; j < 8; j++) acc[i][j] = 0.f;

    for (int kt = 0; kt < Dd; kt += 8) {
        float4 av = *reinterpret_cast<const float4*>(Ap + kt);
        float4 bv;
        if (TRANSB) bv = *reinterpret_cast<const float4*>(Bp + kt);
        else        bv = *reinterpret_cast<const float4*>(Bp + (size_t)kt * Dd);

        __syncthreads();
        As[lcol + 0][lrow] = av.x;
        As[lcol + 1][lrow] = av.y;
        As[lcol + 2][lrow] = av.z;
        As[lcol + 3][lrow] = av.w;
        if (TRANSB) {
            Bs[lcol + 0][lrow] = bv.x;
            Bs[lcol + 1][lrow] = bv.y;
            Bs[lcol + 2][lrow] = bv.z;
            Bs[lcol + 3][lrow] = bv.w;
        } else {
            *reinterpret_cast<float4*>(&Bs[brow][bcol]) = bv;
        }
        __syncthreads();

#pragma unroll
        for (int kk = 0; kk < 8; kk++) {
            float4 a0 = *reinterpret_cast<const float4*>(&As[kk][ty * 4]);
            float4 a1 = *reinterpret_cast<const float4*>(&As[kk][64 + ty * 4]);
            float4 b0 = *reinterpret_cast<const float4*>(&Bs[kk][tx * 4]);
            float4 b1 = *reinterpret_cast<const float4*>(&Bs[kk][64 + tx * 4]);
            float ar[8] = {a0.x, a0.y, a0.z, a0.w, a1.x, a1.y, a1.z, a1.w};
            float br[8] = {b0.x, b0.y, b0.z, b0.w, b1.x, b1.y, b1.z, b1.w};
#pragma unroll
            for (int i = 0; i < 8; i++)
#pragma unroll
                for (int j = 0; j < 8; j++)
                    acc[i][j] += ar[i] * br[j];
        }
    }

    const float stv = EPI ? g_st[n] : 0.f;

#pragma unroll
    for (int bi = 0; bi < 2; bi++) {
#pragma unroll
        for (int i = 0; i < 4; i++) {
            int row = blockIdx.y * 128 + bi * 64 + ty * 4 + i;
#pragma unroll
            for (int bj = 0; bj < 2; bj++) {
                int col = blockIdx.x * 128 + bj * 64 + tx * 4;
                float4 v;
                v.x = acc[bi * 4 + i][bj * 4 + 0];
                v.y = acc[bi * 4 + i][bj * 4 + 1];
                v.z = acc[bi * 4 + i][bj * 4 + 2];
                v.w = acc[bi * 4 + i][bj * 4 + 3];
                if (EPI) {
                    float4 kb = *reinterpret_cast<const float4*>(kfB + (size_t)row * Dd + col);
                    float4 bc = *reinterpret_cast<const float4*>(bcov + (size_t)row * Dd + col);
                    v.x += stv * kb.x + bc.x;
                    v.y += stv * kb.y + bc.y;
                    v.z += stv * kb.z + bc.z;
                    v.w += stv * kb.w + bc.w;
                }
                *reinterpret_cast<float4*>(C + (size_t)row * Dd + col) = v;
            }
        }
    }
}

// ---------------------------------------------------------------------------
// Launch
// inputs: 0=a_mean [64,1024], 1=a_cov [64,1024,1024], 2=weight [1024,1024],
//         3=bias [1024], 4=w_kfacs_A [1024,1024], 5=w_kfacs_B [1024,1024],
//         6=b_cov [1024,1024]
// output: h_mean (65536 floats) followed by h_cov (64*1024*1024 floats)
// ---------------------------------------------------------------------------
extern "C" void kernel_launch(void* const* d_in, const int* in_sizes, int n_in,
                              void* d_out, int out_size)
{
    const float* a_mean = (const float*)d_in[0];
    const float* a_cov  = (const float*)d_in[1];
    const float* weight = (const float*)d_in[2];
    const float* bias   = (const float*)d_in[3];
    const float* kfA    = (const float*)d_in[4];
    const float* kfB    = (const float*)d_in[5];
    const float* bcov   = (const float*)d_in[6];

    float* out_mean = (float*)d_out;
    float* out_cov  = out_mean + (size_t)Bn * Dd;

    float* tmp;
    cudaGetSymbolAddress((void**)&tmp, g_tmp);

    // h_mean
    hmean_kernel<<<dim3(4, Bn), 256>>>(a_mean, weight, bias, out_mean);

    // s + t per batch (two-stage deterministic reduction)
    st_kernel<<<dim3(8, Bn), 256>>>(a_mean, a_cov, kfA);
    st_reduce_kernel<<<1, Bn>>>();

    // tmp[n] = W @ a_cov[n]
    gemm128<false, false><<<dim3(8, 8, Bn), 256>>>(
        weight, a_cov, tmp, nullptr, nullptr,
        0, (size_t)MAT, (size_t)MAT);

    // h_cov[n] = tmp[n] @ W^T + st[n]*kfB + bcov
    gemm128<true, true><<<dim3(8, 8, Bn), 256>>>(
        tmp, weight, out_cov, kfB, bcov,
        (size_t)MAT, 0, (size_t)MAT);
}

// round 3
// speedup vs baseline: 6.6280x; 6.6280x over previous
#include <cuda_runtime.h>
#include <cuda_fp16.h>
#include <cstdint>
#include <cstddef>

#define Bn 64
#define Dd 1024
#define MAT (Dd*Dd)

// -------------------- scratch (device globals) -------------------------------
__device__ __half g_Wh[MAT];                    // W as fp16 (K-major, rows = D_out)
__device__ __half g_cT[(size_t)Bn * MAT];       // covT[n][j][i] = a_cov[n][i][j], fp16
__device__ __half g_tmp[(size_t)Bn * MAT];      // tmp[n][k][j] = (W @ a_cov[n]), fp16
__device__ float  g_part[Bn * 256];
__device__ float  g_st[Bn];

// -------------------- PTX helpers --------------------------------------------
__device__ __forceinline__ void cpa16(uint32_t saddr, const void* g) {
    asm volatile("cp.async.cg.shared.global [%0], [%1], 16;"
                 :: "r"(saddr), "l"(__cvta_generic_to_global(g)) : "memory");
}
__device__ __forceinline__ void cpa_commit() { asm volatile("cp.async.commit_group;" ::: "memory"); }
template<int N> __device__ __forceinline__ void cpa_wait() {
    asm volatile("cp.async.wait_group %0;" :: "n"(N) : "memory");
}
__device__ __forceinline__ void ldsm4(uint32_t* r, uint32_t addr) {
    asm volatile("ldmatrix.sync.aligned.m8n8.x4.shared.b16 {%0,%1,%2,%3}, [%4];"
                 : "=r"(r[0]), "=r"(r[1]), "=r"(r[2]), "=r"(r[3]) : "r"(addr));
}
__device__ __forceinline__ void mma16816(float* c, const uint32_t* a, uint32_t b0, uint32_t b1) {
    asm volatile("mma.sync.aligned.m16n8k16.row.col.f32.f16.f16.f32 "
                 "{%0,%1,%2,%3}, {%4,%5,%6,%7}, {%8,%9}, {%0,%1,%2,%3};"
                 : "+f"(c[0]), "+f"(c[1]), "+f"(c[2]), "+f"(c[3])
                 : "r"(a[0]), "r"(a[1]), "r"(a[2]), "r"(a[3]), "r"(b0), "r"(b1));
}

// -------------------- small kernels ------------------------------------------
__global__ void hmean_kernel(const float* __restrict__ a_mean,
                             const float* __restrict__ W,
                             const float* __restrict__ bias,
                             float* __restrict__ out)
{
    int n = blockIdx.y;
    int k = blockIdx.x * 256 + threadIdx.x;
    __shared__ float sh_a[Dd];
    for (int i = threadIdx.x; i < Dd; i += 256) sh_a[i] = a_mean[n * Dd + i];
    __syncthreads();
    const float4* w4 = reinterpret_cast<const float4*>(W + (size_t)k * Dd);
    float acc = bias[k];
#pragma unroll 8
    for (int i = 0; i < Dd / 4; i++) {
        float4 w = w4[i];
        acc += w.x * sh_a[4*i] + w.y * sh_a[4*i+1] + w.z * sh_a[4*i+2] + w.w * sh_a[4*i+3];
    }
    out[(size_t)n * Dd + k] = acc;
}

__global__ void conv_w(const float* __restrict__ W)
{
    int i = blockIdx.x * 256 + threadIdx.x;     // 256K float4
    float4 v = reinterpret_cast<const float4*>(W)[i];
    __half2* wh = reinterpret_cast<__half2*>(g_Wh);
    wh[2*i]   = __floats2half2_rn(v.x, v.y);
    wh[2*i+1] = __floats2half2_rn(v.z, v.w);
}

// Fused: transpose a_cov -> covT fp16  +  st partials
__global__ __launch_bounds__(256) void transpose_cov(
    const float* __restrict__ a_cov, const float* __restrict__ kfA,
    const float* __restrict__ a_mean)
{
    const int n = blockIdx.z, ti = blockIdx.y, tj = blockIdx.x;
    const int tid = threadIdx.x;
    __shared__ float tile[64][65];
    __shared__ float sa_i[64], sa_j[64], red[256];

    if (tid < 64) sa_i[tid] = a_mean[n * Dd + ti * 64 + tid];
    else if (tid < 128) sa_j[tid - 64] = a_mean[n * Dd + tj * 64 + (tid - 64)];
    __syncthreads();

    const float4* cov4 = reinterpret_cast<const float4*>(a_cov + (size_t)n * MAT);
    const float4* A4   = reinterpret_cast<const float4*>(kfA);
    float local = 0.f;
#pragma unroll
    for (int q = 0; q < 4; q++) {
        int idx = tid + 256 * q;
        int r = idx >> 4, c4 = idx & 15;
        size_t gi = (size_t)(ti * 64 + r) * 256 + tj * 16 + c4;
        float4 cv = cov4[gi];
        float4 av = A4[gi];
        float ai = sa_i[r];
        int jb = c4 * 4;
        local += av.x * (cv.x + ai * sa_j[jb])   + av.y * (cv.y + ai * sa_j[jb+1])
               + av.z * (cv.z + ai * sa_j[jb+2]) + av.w * (cv.w + ai * sa_j[jb+3]);
        tile[r][jb] = cv.x; tile[r][jb+1] = cv.y; tile[r][jb+2] = cv.z; tile[r][jb+3] = cv.w;
    }
    __syncthreads();

#pragma unroll
    for (int q = 0; q < 2; q++) {
        int idx = tid + 256 * q;
        int jj = idx >> 3, sg = idx & 7;
        __half2 hv[4];
#pragma unroll
        for (int e = 0; e < 4; e++)
            hv[e] = __floats2half2_rn(tile[sg * 8 + 2*e][jj], tile[sg * 8 + 2*e + 1][jj]);
        size_t off = (size_t)n * MAT + (size_t)(tj * 64 + jj) * Dd + ti * 64 + sg * 8;
        *reinterpret_cast<uint4*>(g_cT + off) = *reinterpret_cast<uint4*>(hv);
    }

    red[tid] = local;
    __syncthreads();
    for (int s = 128; s > 0; s >>= 1) {
        if (tid < s) red[tid] += red[tid + s];
        __syncthreads();
    }
    if (tid == 0) g_part[n * 256 + ti * 16 + tj] = red[0];
}

__global__ void st_reduce()
{
    __shared__ float red[256];
    int n = blockIdx.x;
    red[threadIdx.x] = g_part[n * 256 + threadIdx.x];
    __syncthreads();
    for (int s = 128; s > 0; s >>= 1) {
        if (threadIdx.x < s) red[threadIdx.x] += red[threadIdx.x + s];
        __syncthreads();
    }
    if (threadIdx.x == 0) g_st[n] = red[0];
}

// -------------------- fp16 mma.sync GEMM -------------------------------------
// D[m,q] = sum_k A[m,k] * B[q,k], both K-major fp16, fp32 accum.
// MODE 0: store fp16 to Ch.   MODE 1: store fp32 + st*kfB + bcov to Cf.
// Block 128x128, BK=64, 8 warps (2x4), warp tile 64x32, 3-stage cp.async.
#define BK 64
#define STAGE_BYTES 32768       // A 16KB + B 16KB per stage (128 rows x 128B each)
#define SMEM_TOTAL (3 * STAGE_BYTES)

template<int MODE>
__global__ __launch_bounds__(256, 2)
void gemm_f16(const __half* __restrict__ Aptr, const __half* __restrict__ Bptr,
              size_t sA, size_t sB,
              __half* __restrict__ Ch, float* __restrict__ Cf,
              const float* __restrict__ kfB, const float* __restrict__ bcov)
{
    extern __shared__ char smem[];
    const uint32_t sbase = (uint32_t)__cvta_generic_to_shared(smem);
    const int tid  = threadIdx.x;
    const int wid  = tid >> 5, lane = tid & 31;
    const int wm   = wid >> 2, wn = wid & 3;      // 2 x 4 warps
    const int n    = blockIdx.z;
    const int m0   = blockIdx.y * 128, n0 = blockIdx.x * 128;
    const __half* A = Aptr + (size_t)n * sA;
    const __half* B = Bptr + (size_t)n * sB;

    float acc[4][4][4];
#pragma unroll
    for (int mt = 0; mt < 4; mt++)
#pragma unroll
        for (int j = 0; j < 4; j++)
#pragma unroll
            for (int e = 0; e < 4; e++) acc[mt][j][e] = 0.f;

    // stage loader: A rows m0..+127, B rows n0..+127, 128B (64 fp16) per row
    auto load_stage = [&](int s, int kt) {
        const uint32_t ab = sbase + s * STAGE_BYTES;
        const uint32_t bb = ab + 16384;
        const int koff = kt * BK;
#pragma unroll
        for (int q = 0; q < 4; q++) {
            int idx = tid + 256 * q;
            int r = idx >> 3, c = idx & 7;
            uint32_t rel = (uint32_t)(r * 128 + c * 16);
            uint32_t swz = rel ^ ((uint32_t)(r & 7) << 4);
            cpa16(ab + swz, A + (size_t)(m0 + r) * Dd + koff + c * 8);
        }
#pragma unroll
        for (int q = 0; q < 4; q++) {
            int idx = tid + 256 * q;
            int r = idx >> 3, c = idx & 7;
            uint32_t rel = (uint32_t)(r * 128 + c * 16);
            uint32_t swz = rel ^ ((uint32_t)(r & 7) << 4);
            cpa16(bb + swz, B + (size_t)(n0 + r) * Dd + koff + c * 8);
        }
        cpa_commit();
    };

    load_stage(0, 0);
    load_stage(1, 1);

    // per-lane ldmatrix address components
    const uint32_t xr    = (uint32_t)(lane & 7) << 4;
    const uint32_t rowA  = (uint32_t)(wm * 64 + (lane & 15)) * 128;
    const uint32_t subA  = (uint32_t)(lane >> 4) * 16;
    const uint32_t rowB  = (uint32_t)(wn * 32 + (lane & 7) + ((lane >> 4) << 3)) * 128;
    const uint32_t kaddB = (uint32_t)((lane >> 3) & 1) * 16;

    const int NT = Dd / BK;   // 16
    for (int kt = 0; kt < NT; kt++) {
        if (kt == NT - 1) cpa_wait<0>(); else cpa_wait<1>();
        __syncthreads();
        if (kt + 2 < NT) load_stage((kt + 2) % 3, kt + 2);

        const uint32_t ab = sbase + (kt % 3) * STAGE_BYTES;
        const uint32_t bb = ab + 16384;
#pragma unroll
        for (int ks = 0; ks < 4; ks++) {
            uint32_t af[4][4], bf[2][4];
            const uint32_t colA = (uint32_t)(ks * 32) + subA;
            const uint32_t colB = (uint32_t)(ks * 32) + kaddB;
#pragma unroll
            for (int mt = 0; mt < 4; mt++)
                ldsm4(af[mt], ab + rowA + (uint32_t)(mt * 2048) + (colA ^ xr));
#pragma unroll
            for (int g = 0; g < 2; g++)
                ldsm4(bf[g], bb + rowB + (uint32_t)(g * 2048) + (colB ^ xr));
#pragma unroll
            for (int mt = 0; mt < 4; mt++)
#pragma unroll
                for (int j = 0; j < 4; j++)
                    mma16816(acc[mt][j], af[mt], bf[j >> 1][(j & 1) * 2], bf[j >> 1][(j & 1) * 2 + 1]);
        }
        __syncthreads();
    }

    // ---- epilogue ----
    const int rbase = m0 + wm * 64 + (lane >> 2);
    const int cbase = n0 + wn * 32 + (lane & 3) * 2;
    if (MODE == 0) {
        __half* out = Ch + (size_t)n * MAT;
#pragma unroll
        for (int mt = 0; mt < 4; mt++) {
#pragma unroll
            for (int j = 0; j < 4; j++) {
                int r = rbase + mt * 16, c = cbase + j * 8;
                *reinterpret_cast<__half2*>(out + (size_t)r * Dd + c) =
                    __floats2half2_rn(acc[mt][j][0], acc[mt][j][1]);
                *reinterpret_cast<__half2*>(out + (size_t)(r + 8) * Dd + c) =
                    __floats2half2_rn(acc[mt][j][2], acc[mt][j][3]);
            }
        }
    } else {
        float* out = Cf + (size_t)n * MAT;
        const float stv = g_st[n];
#pragma unroll
        for (int mt = 0; mt < 4; mt++) {
#pragma unroll
            for (int j = 0; j < 4; j++) {
                int r = rbase + mt * 16, c = cbase + j * 8;
#pragma unroll
                for (int h = 0; h < 2; h++) {
                    int rr = r + h * 8;
                    size_t o = (size_t)rr * Dd + c;
                    float2 kb = *reinterpret_cast<const float2*>(kfB + o);
                    float2 bc = *reinterpret_cast<const float2*>(bcov + o);
                    float2 v;
                    v.x = acc[mt][j][2*h]     + stv * kb.x + bc.x;
                    v.y = acc[mt][j][2*h + 1] + stv * kb.y + bc.y;
                    *reinterpret_cast<float2*>(out + o) = v;
                }
            }
        }
    }
}

// -------------------- launch -------------------------------------------------
extern "C" void kernel_launch(void* const* d_in, const int* in_sizes, int n_in,
                              void* d_out, int out_size)
{
    const float* a_mean = (const float*)d_in[0];
    const float* a_cov  = (const float*)d_in[1];
    const float* weight = (const float*)d_in[2];
    const float* bias   = (const float*)d_in[3];
    const float* kfA    = (const float*)d_in[4];
    const float* kfB    = (const float*)d_in[5];
    const float* bcov   = (const float*)d_in[6];

    float* out_mean = (float*)d_out;
    float* out_cov  = out_mean + (size_t)Bn * Dd;

    void *pWh, *pcT, *ptmp;
    cudaGetSymbolAddress(&pWh, g_Wh);
    cudaGetSymbolAddress(&pcT, g_cT);
    cudaGetSymbolAddress(&ptmp, g_tmp);

    cudaFuncSetAttribute((const void*)gemm_f16<0>, cudaFuncAttributeMaxDynamicSharedMemorySize, SMEM_TOTAL);
    cudaFuncSetAttribute((const void*)gemm_f16<1>, cudaFuncAttributeMaxDynamicSharedMemorySize, SMEM_TOTAL);

    hmean_kernel<<<dim3(4, Bn), 256>>>(a_mean, weight, bias, out_mean);
    conv_w<<<1024, 256>>>(weight);
    transpose_cov<<<dim3(16, 16, Bn), 256>>>(a_cov, kfA, a_mean);
    st_reduce<<<Bn, 256>>>();

    // GEMM1: tmp[n][k][j] = sum_i W[k,i] * covT[n][j,i]
    gemm_f16<0><<<dim3(8, 8, Bn), 256, SMEM_TOTAL>>>(
        (const __half*)pWh, (const __half*)pcT, 0, (size_t)MAT,
        (__half*)ptmp, nullptr, nullptr, nullptr);

    // GEMM2: h_cov[n][k][l] = sum_j tmp[n][k,j] * W[l,j] + st[n]*kfB + bcov
    gemm_f16<1><<<dim3(8, 8, Bn), 256, SMEM_TOTAL>>>(
        (const __half*)ptmp, (const __half*)pWh, (size_t)MAT, 0,
        nullptr, out_cov, kfB, bcov);
}